// round 5
// baseline (speedup 1.0000x reference)
#include <cuda_runtime.h>
#include <cstdint>

#define NN 50000

// ---------------- scratch (no allocations allowed) ----------------
static __device__ __align__(16) float g_A1[NN * 128];   // [agg(x) 0..63 | x 64..127]
static __device__ __align__(16) float g_A2[NN * 256];   // [agg(h) 0..127 | h 128..255]
static __device__ float g_deg[NN];
static __device__ __align__(16) float g_Ws1[128 * 128]; // [W_l1 ; W_r1]
static __device__ __align__(16) float g_Ws2[256 * 304]; // [W_l2 ; W_r2], padded 300->304
static __device__ int g_idx64;                          // 1 if edge_index is int64

// ---------------- threefry2x32 dropout, JAX partitionable mode ----------------
// partitionable random_bits(32): counts = iota(u64); (hi,lo)=(idx>>32, idx);
// (o0,o1) = threefry2x32(key=(0,42), (hi,lo)); bits = o0 ^ o1  (32-bit path).
__device__ __forceinline__ float tf_drop(float v, unsigned idx) {
    unsigned x0 = 0u, x1 = idx;
    const unsigned k0 = 0u, k1 = 42u;
    const unsigned k2c = 0u ^ 42u ^ 0x1BD11BDAu;
    x0 += k0; x1 += k1;
#define TF_R(r) { x0 += x1; x1 = __funnelshift_l(x1, x1, (r)); x1 ^= x0; }
    TF_R(13) TF_R(15) TF_R(26) TF_R(6)
    x0 += k1;  x1 += k2c + 1u;
    TF_R(17) TF_R(29) TF_R(16) TF_R(24)
    x0 += k2c; x1 += k0 + 2u;
    TF_R(13) TF_R(15) TF_R(26) TF_R(6)
    x0 += k0;  x1 += k1 + 3u;
    TF_R(17) TF_R(29) TF_R(16) TF_R(24)
    x0 += k1;  x1 += k2c + 4u;
    TF_R(13) TF_R(15) TF_R(26) TF_R(6)
    x0 += k2c; x1 += k0 + 5u;
#undef TF_R
    unsigned bits = x0 ^ x1;   // 32-bit partitionable path: out0 ^ out1
    float u = __uint_as_float((bits >> 9) | 0x3f800000u) - 1.0f;
    return (u < 0.5f) ? v * 2.0f : 0.0f;
}

// ---------------- dtype detection for edge_index ----------------
__global__ void k_detect(const void* __restrict__ ei) {
    const long long* p = (const long long*)ei;
    long long v = p[threadIdx.x];
    unsigned bad = __ballot_sync(0xffffffffu, (unsigned long long)v >= (unsigned long long)NN);
    __shared__ int s_bad;
    if (threadIdx.x == 0) s_bad = 0;
    __syncthreads();
    if ((threadIdx.x & 31) == 0 && bad) atomicOr(&s_bad, 1);
    __syncthreads();
    if (threadIdx.x == 0) g_idx64 = s_bad ? 0 : 1;
}

__device__ __forceinline__ void load_edge(const void* ei, int E, int e,
                                          int& src, int& dst) {
    if (g_idx64) {
        const long long* p = (const long long*)ei;
        src = (int)p[e];
        dst = (int)p[E + e];
    } else {
        const int* p = (const int*)ei;
        src = p[e];
        dst = p[E + e];
    }
}

// ---------------- init: zero aggs/deg, copy x, stack weights ----------------
__global__ void k_init(const float* __restrict__ x,
                       const float* __restrict__ Wl1, const float* __restrict__ Wr1,
                       const float* __restrict__ Wl2, const float* __restrict__ Wr2) {
    const int T0 = NN * 64;
    const int T1 = T0 + NN * 128;
    const int T2 = T1 + NN;
    const int T3 = T2 + 128 * 128;
    const int T4 = T3 + 256 * 304;
    for (int i = blockIdx.x * blockDim.x + threadIdx.x; i < T4;
         i += gridDim.x * blockDim.x) {
        if (i < T0) {
            int row = i >> 6, col = i & 63;
            g_A1[row * 128 + col] = 0.f;
            g_A1[row * 128 + 64 + col] = x[i];
        } else if (i < T1) {
            int j = i - T0;
            g_A2[(j >> 7) * 256 + (j & 127)] = 0.f;
        } else if (i < T2) {
            g_deg[i - T1] = 0.f;
        } else if (i < T3) {
            int j = i - T2;
            g_Ws1[j] = (j < 64 * 128) ? Wl1[j] : Wr1[j - 64 * 128];
        } else {
            int j = i - T3;
            int row = j / 304, col = j - row * 304;
            float v = 0.f;
            if (col < 300)
                v = (row < 128) ? Wl2[row * 300 + col] : Wr2[(row - 128) * 300 + col];
            g_Ws2[j] = v;
        }
    }
}

// ---------------- edge scatter, layer 1: agg x (64 floats / edge, 16 thr) ----------------
__global__ void __launch_bounds__(256) k_scatter1(const void* __restrict__ ei, int E) {
    int gid = blockIdx.x * 256 + threadIdx.x;
    int e = gid >> 4;
    if (e >= E) return;
    int part = gid & 15;
    int src, dst;
    load_edge(ei, E, e, src, dst);
    if ((unsigned)src >= NN || (unsigned)dst >= NN) return;
    float4 v = *(const float4*)(g_A1 + src * 128 + 64 + part * 4);
    float* p = g_A1 + dst * 128 + part * 4;
    asm volatile("red.global.add.v4.f32 [%0], {%1,%2,%3,%4};"
                 :: "l"(p), "f"(v.x), "f"(v.y), "f"(v.z), "f"(v.w) : "memory");
    if (part == 0) atomicAdd(g_deg + dst, 1.0f);
}

// ---------------- edge scatter, layer 2: agg h (128 floats / edge, 32 thr) ----------------
__global__ void __launch_bounds__(256) k_scatter2(const void* __restrict__ ei, int E) {
    int gid = blockIdx.x * 256 + threadIdx.x;
    int e = gid >> 5;
    if (e >= E) return;
    int part = gid & 31;
    int src, dst;
    load_edge(ei, E, e, src, dst);
    if ((unsigned)src >= NN || (unsigned)dst >= NN) return;
    float4 v = *(const float4*)(g_A2 + (long long)src * 256 + 128 + part * 4);
    float* p = g_A2 + (long long)dst * 256 + part * 4;
    asm volatile("red.global.add.v4.f32 [%0], {%1,%2,%3,%4};"
                 :: "l"(p), "f"(v.x), "f"(v.y), "f"(v.z), "f"(v.w) : "memory");
}

// ---------------- divide agg parts by max(deg,1) ----------------
__global__ void k_scale1() {
    int gid = blockIdx.x * blockDim.x + threadIdx.x;
    if (gid >= NN * 16) return;
    int row = gid >> 4, c4 = gid & 15;
    float inv = 1.0f / fmaxf(g_deg[row], 1.0f);
    float4* p = (float4*)(g_A1 + row * 128) + c4;
    float4 v = *p;
    v.x *= inv; v.y *= inv; v.z *= inv; v.w *= inv;
    *p = v;
}

__global__ void k_scale2() {
    int gid = blockIdx.x * blockDim.x + threadIdx.x;
    if (gid >= NN * 32) return;
    int row = gid >> 5, c4 = gid & 31;
    float inv = 1.0f / fmaxf(g_deg[row], 1.0f);
    float4* p = (float4*)(g_A2 + (long long)row * 256) + c4;
    float4 v = *p;
    v.x *= inv; v.y *= inv; v.z *= inv; v.w *= inv;
    *p = v;
}

// ---------------- GEMM layer 1: h = relu(A1 @ Ws1 + b1), dropout, -> A2[:,128:256] ----------------
__global__ void __launch_bounds__(256) k_gemm1(const float* __restrict__ b1) {
    __shared__ float sA[64 * 32];
    __shared__ float sW[32 * 128];
    int tid = threadIdx.x;
    int row0 = blockIdx.x * 64;
    int cg = tid & 31;   // cols cg*4 .. cg*4+3
    int rg = tid >> 5;   // rows rg*8 .. rg*8+7
    float acc[8][4];
#pragma unroll
    for (int r = 0; r < 8; r++)
#pragma unroll
        for (int j = 0; j < 4; j++) acc[r][j] = 0.f;

    for (int ks = 0; ks < 128; ks += 32) {
        __syncthreads();
#pragma unroll
        for (int i = tid; i < 512; i += 256) {       // A tile 64x32
            int r = i >> 3, c4 = i & 7;
            int gr = row0 + r;
            float4 v = (gr < NN) ? *(const float4*)(g_A1 + gr * 128 + ks + c4 * 4)
                                 : make_float4(0.f, 0.f, 0.f, 0.f);
            *(float4*)(sA + r * 32 + c4 * 4) = v;
        }
#pragma unroll
        for (int i = tid; i < 1024; i += 256) {      // W tile 32x128
            int r = i >> 5, c4 = i & 31;
            *(float4*)(sW + r * 128 + c4 * 4) =
                *(const float4*)(g_Ws1 + (ks + r) * 128 + c4 * 4);
        }
        __syncthreads();
#pragma unroll
        for (int k4 = 0; k4 < 32; k4 += 4) {
            float4 a[8];
#pragma unroll
            for (int r = 0; r < 8; r++)
                a[r] = *(const float4*)(sA + (rg * 8 + r) * 32 + k4);
#pragma unroll
            for (int kk = 0; kk < 4; kk++) {
                float4 w = *(const float4*)(sW + (k4 + kk) * 128 + cg * 4);
#pragma unroll
                for (int r = 0; r < 8; r++) {
                    float av = ((const float*)&a[r])[kk];
                    acc[r][0] += av * w.x;
                    acc[r][1] += av * w.y;
                    acc[r][2] += av * w.z;
                    acc[r][3] += av * w.w;
                }
            }
        }
    }
    int c0 = cg * 4;
    float4 bv = *(const float4*)(b1 + c0);
#pragma unroll
    for (int r = 0; r < 8; r++) {
        int grow = row0 + rg * 8 + r;
        if (grow >= NN) continue;
        float4 h;
        h.x = fmaxf(acc[r][0] + bv.x, 0.f);
        h.y = fmaxf(acc[r][1] + bv.y, 0.f);
        h.z = fmaxf(acc[r][2] + bv.z, 0.f);
        h.w = fmaxf(acc[r][3] + bv.w, 0.f);
        unsigned base = (unsigned)grow * 128u + (unsigned)c0;
        h.x = tf_drop(h.x, base + 0u);
        h.y = tf_drop(h.y, base + 1u);
        h.z = tf_drop(h.z, base + 2u);
        h.w = tf_drop(h.w, base + 3u);
        *(float4*)(g_A2 + (long long)grow * 256 + 128 + c0) = h;
    }
}

// ---------------- GEMM layer 2: out = A2 @ Ws2 + b2 (logits) ----------------
__global__ void __launch_bounds__(256) k_gemm2(const float* __restrict__ b2,
                                               float* __restrict__ out) {
    __shared__ float sA[64 * 64];
    __shared__ float sW[64 * 64];
    int tid = threadIdx.x;
    int row0 = blockIdx.x * 64;
    int col0 = blockIdx.y * 64;
    int cg = tid & 31;   // cols col0 + cg*2
    int rg = tid >> 5;   // rows rg*8..
    float acc[8][2];
#pragma unroll
    for (int r = 0; r < 8; r++) { acc[r][0] = 0.f; acc[r][1] = 0.f; }

    for (int ks = 0; ks < 256; ks += 64) {
        __syncthreads();
#pragma unroll
        for (int i = tid; i < 1024; i += 256) {      // A tile 64x64
            int r = i >> 4, c4 = i & 15;
            int gr = row0 + r;
            float4 v = (gr < NN)
                ? *(const float4*)(g_A2 + (long long)gr * 256 + ks + c4 * 4)
                : make_float4(0.f, 0.f, 0.f, 0.f);
            *(float4*)(sA + r * 64 + c4 * 4) = v;
        }
#pragma unroll
        for (int i = tid; i < 1024; i += 256) {      // W tile 64x64
            int r = i >> 4, c4 = i & 15;
            int gc = col0 + c4 * 4;
            float4 v = (gc < 304)
                ? *(const float4*)(g_Ws2 + (ks + r) * 304 + gc)
                : make_float4(0.f, 0.f, 0.f, 0.f);
            *(float4*)(sW + r * 64 + c4 * 4) = v;
        }
        __syncthreads();
#pragma unroll
        for (int k4 = 0; k4 < 64; k4 += 4) {
            float4 a[8];
#pragma unroll
            for (int r = 0; r < 8; r++)
                a[r] = *(const float4*)(sA + (rg * 8 + r) * 64 + k4);
#pragma unroll
            for (int kk = 0; kk < 4; kk++) {
                float2 w = *(const float2*)(sW + (k4 + kk) * 64 + cg * 2);
#pragma unroll
                for (int r = 0; r < 8; r++) {
                    float av = ((const float*)&a[r])[kk];
                    acc[r][0] += av * w.x;
                    acc[r][1] += av * w.y;
                }
            }
        }
    }
    int c0 = col0 + cg * 2;
    if (c0 < 300) {
        float2 bv = *(const float2*)(b2 + c0);
#pragma unroll
        for (int r = 0; r < 8; r++) {
            int grow = row0 + rg * 8 + r;
            if (grow >= NN) continue;
            float2 o;
            o.x = acc[r][0] + bv.x;
            o.y = acc[r][1] + bv.y;
            *(float2*)(out + (long long)grow * 300 + c0) = o;
        }
    }
}

// ---------------- log_softmax in-place, one warp per row of 300 ----------------
__global__ void __launch_bounds__(256) k_logsoftmax(float* __restrict__ out) {
    int gid = blockIdx.x * 256 + threadIdx.x;
    int row = gid >> 5;
    int lane = gid & 31;
    if (row >= NN) return;
    float* p = out + (long long)row * 300;
    float vals[10];
    float m = -3.4e38f;
#pragma unroll
    for (int i = 0; i < 10; i++) {
        int c = lane + i * 32;
        vals[i] = (c < 300) ? p[c] : -3.4e38f;
        m = fmaxf(m, vals[i]);
    }
#pragma unroll
    for (int o = 16; o; o >>= 1) m = fmaxf(m, __shfl_xor_sync(0xffffffffu, m, o));
    float s = 0.f;
#pragma unroll
    for (int i = 0; i < 10; i++) {
        int c = lane + i * 32;
        if (c < 300) s += __expf(vals[i] - m);
    }
#pragma unroll
    for (int o = 16; o; o >>= 1) s += __shfl_xor_sync(0xffffffffu, s, o);
    float lse = m + __logf(s);
#pragma unroll
    for (int i = 0; i < 10; i++) {
        int c = lane + i * 32;
        if (c < 300) p[c] = vals[i] - lse;
    }
}

// ---------------- launch ----------------
extern "C" void kernel_launch(void* const* d_in, const int* in_sizes, int n_in,
                              void* d_out, int out_size) {
    const float* x        = (const float*)d_in[0];
    const void*  ei       = (const void*)d_in[1];
    const float* Wl1      = (const float*)d_in[2];
    const float* Wr1      = (const float*)d_in[3];
    const float* b1       = (const float*)d_in[4];
    const float* Wl2      = (const float*)d_in[5];
    const float* Wr2      = (const float*)d_in[6];
    const float* b2       = (const float*)d_in[7];
    float* out            = (float*)d_out;
    int E = in_sizes[1] / 2;

    k_detect<<<1, 256>>>(ei);
    k_init<<<4096, 256>>>(x, Wl1, Wr1, Wl2, Wr2);
    k_scatter1<<<(E * 16 + 255) / 256, 256>>>(ei, E);
    k_scale1<<<(NN * 16 + 255) / 256, 256>>>();
    k_gemm1<<<(NN + 63) / 64, 256>>>(b1);
    k_scatter2<<<(E * 32 + 255) / 256, 256>>>(ei, E);
    k_scale2<<<(NN * 32 + 255) / 256, 256>>>();
    dim3 g2((NN + 63) / 64, 5);
    k_gemm2<<<g2, 256>>>(b2, out);
    k_logsoftmax<<<(NN * 32 + 255) / 256, 256>>>(out);
}

// round 7
// speedup vs baseline: 1.0334x; 1.0334x over previous
#include <cuda_runtime.h>
#include <cstdint>

#define NN 50000
#define EMAX 1000000

// ---------------- scratch (no allocations allowed) ----------------
static __device__ __align__(16) float g_A1[NN * 128];   // [agg(x) 0..63 | x 64..127]
static __device__ __align__(16) float g_A2[NN * 256];   // [agg(h) 0..127 | h 128..255]
static __device__ __align__(16) float g_Ws1[128 * 128]; // [W_l1 ; W_r1]
static __device__ __align__(16) float g_Ws2[256 * 304]; // [W_l2 ; W_r2], padded 300->304
static __device__ int g_idx64;                          // 1 if edge_index is int64
static __device__ int g_degi[NN];                       // in-degree (histogram)
static __device__ int g_rowptr[NN + 1];                 // CSR row pointers (by dst)
static __device__ int g_cursor[NN];                     // placement cursors
static __device__ int g_colsrc[EMAX];                   // CSR column (src) indices

// ---------------- threefry2x32 dropout, JAX partitionable mode ----------------
// bits(idx) = o0 ^ o1 of threefry2x32(key=(0,42), counts=(0, idx)).
__device__ __forceinline__ float tf_drop(float v, unsigned idx) {
    unsigned x0 = 0u, x1 = idx;
    const unsigned k0 = 0u, k1 = 42u;
    const unsigned k2c = 0u ^ 42u ^ 0x1BD11BDAu;
    x0 += k0; x1 += k1;
#define TF_R(r) { x0 += x1; x1 = __funnelshift_l(x1, x1, (r)); x1 ^= x0; }
    TF_R(13) TF_R(15) TF_R(26) TF_R(6)
    x0 += k1;  x1 += k2c + 1u;
    TF_R(17) TF_R(29) TF_R(16) TF_R(24)
    x0 += k2c; x1 += k0 + 2u;
    TF_R(13) TF_R(15) TF_R(26) TF_R(6)
    x0 += k0;  x1 += k1 + 3u;
    TF_R(17) TF_R(29) TF_R(16) TF_R(24)
    x0 += k1;  x1 += k2c + 4u;
    TF_R(13) TF_R(15) TF_R(26) TF_R(6)
    x0 += k2c; x1 += k0 + 5u;
#undef TF_R
    unsigned bits = x0 ^ x1;
    float u = __uint_as_float((bits >> 9) | 0x3f800000u) - 1.0f;
    return (u < 0.5f) ? v * 2.0f : 0.0f;
}

// ---------------- dtype detection for edge_index ----------------
__global__ void k_detect(const void* __restrict__ ei) {
    const long long* p = (const long long*)ei;
    long long v = p[threadIdx.x];
    unsigned bad = __ballot_sync(0xffffffffu, (unsigned long long)v >= (unsigned long long)NN);
    __shared__ int s_bad;
    if (threadIdx.x == 0) s_bad = 0;
    __syncthreads();
    if ((threadIdx.x & 31) == 0 && bad) atomicOr(&s_bad, 1);
    __syncthreads();
    if (threadIdx.x == 0) g_idx64 = s_bad ? 0 : 1;
}

__device__ __forceinline__ void load_edge(const void* ei, int E, int e,
                                          int& src, int& dst) {
    if (g_idx64) {
        const long long* p = (const long long*)ei;
        src = (int)p[e];
        dst = (int)p[E + e];
    } else {
        const int* p = (const int*)ei;
        src = p[e];
        dst = p[E + e];
    }
}

// ---------------- init: copy x, zero deg, stack weights ----------------
__global__ void k_init(const float* __restrict__ x,
                       const float* __restrict__ Wl1, const float* __restrict__ Wr1,
                       const float* __restrict__ Wl2, const float* __restrict__ Wr2) {
    const int T0 = NN * 64;
    const int T1 = T0 + NN;
    const int T2 = T1 + 128 * 128;
    const int T3 = T2 + 256 * 304;
    for (int i = blockIdx.x * blockDim.x + threadIdx.x; i < T3;
         i += gridDim.x * blockDim.x) {
        if (i < T0) {
            int row = i >> 6, col = i & 63;
            g_A1[row * 128 + 64 + col] = x[i];
        } else if (i < T1) {
            g_degi[i - T0] = 0;
        } else if (i < T2) {
            int j = i - T1;
            g_Ws1[j] = (j < 64 * 128) ? Wl1[j] : Wr1[j - 64 * 128];
        } else {
            int j = i - T2;
            int row = j / 304, col = j - row * 304;
            float v = 0.f;
            if (col < 300)
                v = (row < 128) ? Wl2[row * 300 + col] : Wr2[(row - 128) * 300 + col];
            g_Ws2[j] = v;
        }
    }
}

// ---------------- CSR build ----------------
__global__ void k_hist(const void* __restrict__ ei, int E) {
    int e = blockIdx.x * blockDim.x + threadIdx.x;
    if (e >= E) return;
    int src, dst;
    load_edge(ei, E, e, src, dst);
    if ((unsigned)dst >= NN) return;
    atomicAdd(&g_degi[dst], 1);
}

__global__ void __launch_bounds__(1024) k_scan() {
    __shared__ int part[1024];
    int t = threadIdx.x;
    const int CH = (NN + 1023) / 1024;   // 49
    int beg = t * CH;
    int end = min(beg + CH, NN);
    int s = 0;
    for (int i = beg; i < end; i++) s += g_degi[i];
    part[t] = s;
    __syncthreads();
    // inclusive Hillis-Steele scan
    for (int off = 1; off < 1024; off <<= 1) {
        int v = (t >= off) ? part[t - off] : 0;
        __syncthreads();
        part[t] += v;
        __syncthreads();
    }
    int run = (t == 0) ? 0 : part[t - 1];
    for (int i = beg; i < end; i++) {
        g_rowptr[i] = run;
        g_cursor[i] = run;
        run += g_degi[i];
    }
    if (t == 1023) g_rowptr[NN] = part[1023];
}

__global__ void k_place(const void* __restrict__ ei, int E) {
    int e = blockIdx.x * blockDim.x + threadIdx.x;
    if (e >= E) return;
    int src, dst;
    load_edge(ei, E, e, src, dst);
    if ((unsigned)src >= NN || (unsigned)dst >= NN) return;
    int pos = atomicAdd(&g_cursor[dst], 1);
    if (pos < EMAX) g_colsrc[pos] = src;
}

// ---------------- gather-aggregate, layer 1: mean of x over in-neighbors ----------------
// warp per node; lane covers 2 floats of the 64-dim feature.
__global__ void __launch_bounds__(256) k_gather1() {
    int warp = blockIdx.x * 8 + (threadIdx.x >> 5);
    int lane = threadIdx.x & 31;
    if (warp >= NN) return;
    int n0 = g_rowptr[warp], n1 = g_rowptr[warp + 1];
    float2 acc = make_float2(0.f, 0.f);
    for (int jb = n0; jb < n1; jb += 32) {
        int sid = (jb + lane < n1) ? g_colsrc[jb + lane] : 0;
        int m = min(32, n1 - jb);
        for (int k = 0; k < m; k++) {
            int s = __shfl_sync(0xffffffffu, sid, k);
            float2 v = *(const float2*)(g_A1 + s * 128 + 64 + lane * 2);
            acc.x += v.x; acc.y += v.y;
        }
    }
    float inv = 1.0f / fmaxf((float)(n1 - n0), 1.0f);
    acc.x *= inv; acc.y *= inv;
    *(float2*)(g_A1 + warp * 128 + lane * 2) = acc;
}

// ---------------- gather-aggregate, layer 2: mean of h over in-neighbors ----------------
// warp per node; lane covers 4 floats of the 128-dim feature.
__global__ void __launch_bounds__(256) k_gather2() {
    int warp = blockIdx.x * 8 + (threadIdx.x >> 5);
    int lane = threadIdx.x & 31;
    if (warp >= NN) return;
    int n0 = g_rowptr[warp], n1 = g_rowptr[warp + 1];
    float4 acc = make_float4(0.f, 0.f, 0.f, 0.f);
    for (int jb = n0; jb < n1; jb += 32) {
        int sid = (jb + lane < n1) ? g_colsrc[jb + lane] : 0;
        int m = min(32, n1 - jb);
        for (int k = 0; k < m; k++) {
            int s = __shfl_sync(0xffffffffu, sid, k);
            float4 v = *(const float4*)(g_A2 + (long long)s * 256 + 128 + lane * 4);
            acc.x += v.x; acc.y += v.y; acc.z += v.z; acc.w += v.w;
        }
    }
    float inv = 1.0f / fmaxf((float)(n1 - n0), 1.0f);
    acc.x *= inv; acc.y *= inv; acc.z *= inv; acc.w *= inv;
    *(float4*)(g_A2 + (long long)warp * 256 + lane * 4) = acc;
}

// ---------------- GEMM layer 1: h = relu(A1 @ Ws1 + b1), dropout, -> A2[:,128:256] ----------------
__global__ void __launch_bounds__(256) k_gemm1(const float* __restrict__ b1) {
    __shared__ float sA[64 * 32];
    __shared__ float sW[32 * 128];
    int tid = threadIdx.x;
    int row0 = blockIdx.x * 64;
    int cg = tid & 31;
    int rg = tid >> 5;
    float acc[8][4];
#pragma unroll
    for (int r = 0; r < 8; r++)
#pragma unroll
        for (int j = 0; j < 4; j++) acc[r][j] = 0.f;

    for (int ks = 0; ks < 128; ks += 32) {
        __syncthreads();
#pragma unroll
        for (int i = tid; i < 512; i += 256) {
            int r = i >> 3, c4 = i & 7;
            int gr = row0 + r;
            float4 v = (gr < NN) ? *(const float4*)(g_A1 + gr * 128 + ks + c4 * 4)
                                 : make_float4(0.f, 0.f, 0.f, 0.f);
            *(float4*)(sA + r * 32 + c4 * 4) = v;
        }
#pragma unroll
        for (int i = tid; i < 1024; i += 256) {
            int r = i >> 5, c4 = i & 31;
            *(float4*)(sW + r * 128 + c4 * 4) =
                *(const float4*)(g_Ws1 + (ks + r) * 128 + c4 * 4);
        }
        __syncthreads();
#pragma unroll
        for (int k4 = 0; k4 < 32; k4 += 4) {
            float4 a[8];
#pragma unroll
            for (int r = 0; r < 8; r++)
                a[r] = *(const float4*)(sA + (rg * 8 + r) * 32 + k4);
#pragma unroll
            for (int kk = 0; kk < 4; kk++) {
                float4 w = *(const float4*)(sW + (k4 + kk) * 128 + cg * 4);
#pragma unroll
                for (int r = 0; r < 8; r++) {
                    float av = ((const float*)&a[r])[kk];
                    acc[r][0] += av * w.x;
                    acc[r][1] += av * w.y;
                    acc[r][2] += av * w.z;
                    acc[r][3] += av * w.w;
                }
            }
        }
    }
    int c0 = cg * 4;
    float4 bv = *(const float4*)(b1 + c0);
#pragma unroll
    for (int r = 0; r < 8; r++) {
        int grow = row0 + rg * 8 + r;
        if (grow >= NN) continue;
        float4 h;
        h.x = fmaxf(acc[r][0] + bv.x, 0.f);
        h.y = fmaxf(acc[r][1] + bv.y, 0.f);
        h.z = fmaxf(acc[r][2] + bv.z, 0.f);
        h.w = fmaxf(acc[r][3] + bv.w, 0.f);
        unsigned base = (unsigned)grow * 128u + (unsigned)c0;
        h.x = tf_drop(h.x, base + 0u);
        h.y = tf_drop(h.y, base + 1u);
        h.z = tf_drop(h.z, base + 2u);
        h.w = tf_drop(h.w, base + 3u);
        *(float4*)(g_A2 + (long long)grow * 256 + 128 + c0) = h;
    }
}

// ---------------- GEMM layer 2: out = A2 @ Ws2 + b2 (logits) ----------------
__global__ void __launch_bounds__(256) k_gemm2(const float* __restrict__ b2,
                                               float* __restrict__ out) {
    __shared__ float sA[64 * 64];
    __shared__ float sW[64 * 64];
    int tid = threadIdx.x;
    int row0 = blockIdx.x * 64;
    int col0 = blockIdx.y * 64;
    int cg = tid & 31;
    int rg = tid >> 5;
    float acc[8][2];
#pragma unroll
    for (int r = 0; r < 8; r++) { acc[r][0] = 0.f; acc[r][1] = 0.f; }

    for (int ks = 0; ks < 256; ks += 64) {
        __syncthreads();
#pragma unroll
        for (int i = tid; i < 1024; i += 256) {
            int r = i >> 4, c4 = i & 15;
            int gr = row0 + r;
            float4 v = (gr < NN)
                ? *(const float4*)(g_A2 + (long long)gr * 256 + ks + c4 * 4)
                : make_float4(0.f, 0.f, 0.f, 0.f);
            *(float4*)(sA + r * 64 + c4 * 4) = v;
        }
#pragma unroll
        for (int i = tid; i < 1024; i += 256) {
            int r = i >> 4, c4 = i & 15;
            int gc = col0 + c4 * 4;
            float4 v = (gc < 304)
                ? *(const float4*)(g_Ws2 + (ks + r) * 304 + gc)
                : make_float4(0.f, 0.f, 0.f, 0.f);
            *(float4*)(sW + r * 64 + c4 * 4) = v;
        }
        __syncthreads();
#pragma unroll
        for (int k4 = 0; k4 < 64; k4 += 4) {
            float4 a[8];
#pragma unroll
            for (int r = 0; r < 8; r++)
                a[r] = *(const float4*)(sA + (rg * 8 + r) * 64 + k4);
#pragma unroll
            for (int kk = 0; kk < 4; kk++) {
                float2 w = *(const float2*)(sW + (k4 + kk) * 64 + cg * 2);
#pragma unroll
                for (int r = 0; r < 8; r++) {
                    float av = ((const float*)&a[r])[kk];
                    acc[r][0] += av * w.x;
                    acc[r][1] += av * w.y;
                }
            }
        }
    }
    int c0 = col0 + cg * 2;
    if (c0 < 300) {
        float2 bv = *(const float2*)(b2 + c0);
#pragma unroll
        for (int r = 0; r < 8; r++) {
            int grow = row0 + rg * 8 + r;
            if (grow >= NN) continue;
            float2 o;
            o.x = acc[r][0] + bv.x;
            o.y = acc[r][1] + bv.y;
            *(float2*)(out + (long long)grow * 300 + c0) = o;
        }
    }
}

// ---------------- log_softmax in-place, one warp per row of 300 ----------------
__global__ void __launch_bounds__(256) k_logsoftmax(float* __restrict__ out) {
    int gid = blockIdx.x * 256 + threadIdx.x;
    int row = gid >> 5;
    int lane = gid & 31;
    if (row >= NN) return;
    float* p = out + (long long)row * 300;
    float vals[10];
    float m = -3.4e38f;
#pragma unroll
    for (int i = 0; i < 10; i++) {
        int c = lane + i * 32;
        vals[i] = (c < 300) ? p[c] : -3.4e38f;
        m = fmaxf(m, vals[i]);
    }
#pragma unroll
    for (int o = 16; o; o >>= 1) m = fmaxf(m, __shfl_xor_sync(0xffffffffu, m, o));
    float s = 0.f;
#pragma unroll
    for (int i = 0; i < 10; i++) {
        int c = lane + i * 32;
        if (c < 300) s += __expf(vals[i] - m);
    }
#pragma unroll
    for (int o = 16; o; o >>= 1) s += __shfl_xor_sync(0xffffffffu, s, o);
    float lse = m + __logf(s);
#pragma unroll
    for (int i = 0; i < 10; i++) {
        int c = lane + i * 32;
        if (c < 300) p[c] = vals[i] - lse;
    }
}

// ---------------- launch ----------------
extern "C" void kernel_launch(void* const* d_in, const int* in_sizes, int n_in,
                              void* d_out, int out_size) {
    const float* x        = (const float*)d_in[0];
    const void*  ei       = (const void*)d_in[1];
    const float* Wl1      = (const float*)d_in[2];
    const float* Wr1      = (const float*)d_in[3];
    const float* b1       = (const float*)d_in[4];
    const float* Wl2      = (const float*)d_in[5];
    const float* Wr2      = (const float*)d_in[6];
    const float* b2       = (const float*)d_in[7];
    float* out            = (float*)d_out;
    int E = in_sizes[1] / 2;

    k_detect<<<1, 256>>>(ei);
    k_init<<<4096, 256>>>(x, Wl1, Wr1, Wl2, Wr2);
    k_hist<<<(E + 255) / 256, 256>>>(ei, E);
    k_scan<<<1, 1024>>>();
    k_place<<<(E + 255) / 256, 256>>>(ei, E);
    k_gather1<<<(NN + 7) / 8, 256>>>();
    k_gemm1<<<(NN + 63) / 64, 256>>>(b1);
    k_gather2<<<(NN + 7) / 8, 256>>>();
    dim3 g2((NN + 63) / 64, 5);
    k_gemm2<<<g2, 256>>>(b2, out);
    k_logsoftmax<<<(NN * 32 + 255) / 256, 256>>>(out);
}

// round 8
// speedup vs baseline: 1.2296x; 1.1898x over previous
#include <cuda_runtime.h>
#include <cstdint>

#define NN 50000
#define EMAX 1000000
#define SCAN_NB ((NN + 511) / 512)   // 98 chunks of 512

// ---------------- scratch (no allocations allowed) ----------------
static __device__ __align__(16) float g_A1[NN * 128];   // [agg(x) 0..63 | x 64..127]
static __device__ __align__(16) float g_A2[NN * 256];   // [agg(h) 0..127 | h 128..255]
static __device__ __align__(16) float g_Ws1[128 * 128]; // [W_l1 ; W_r1]
static __device__ __align__(16) float g_Ws2[256 * 304]; // [W_l2 ; W_r2], padded 300->304
static __device__ int g_idx64;                          // 1 if edge_index is int64
static __device__ int g_degi[NN];                       // in-degree (histogram)
static __device__ int g_rowptr[NN + 1];                 // CSR row pointers (by dst)
static __device__ int g_cursor[NN];                     // placement cursors
static __device__ int g_colsrc[EMAX];                   // CSR column (src) indices
static __device__ int g_part[128];                      // per-chunk sums
static __device__ int g_partoff[128];                   // exclusive chunk offsets

// ---------------- threefry2x32 dropout, JAX partitionable mode ----------------
// bits(idx) = o0 ^ o1 of threefry2x32(key=(0,42), counts=(0, idx)).
__device__ __forceinline__ float tf_drop(float v, unsigned idx) {
    unsigned x0 = 0u, x1 = idx;
    const unsigned k0 = 0u, k1 = 42u;
    const unsigned k2c = 0u ^ 42u ^ 0x1BD11BDAu;
    x0 += k0; x1 += k1;
#define TF_R(r) { x0 += x1; x1 = __funnelshift_l(x1, x1, (r)); x1 ^= x0; }
    TF_R(13) TF_R(15) TF_R(26) TF_R(6)
    x0 += k1;  x1 += k2c + 1u;
    TF_R(17) TF_R(29) TF_R(16) TF_R(24)
    x0 += k2c; x1 += k0 + 2u;
    TF_R(13) TF_R(15) TF_R(26) TF_R(6)
    x0 += k0;  x1 += k1 + 3u;
    TF_R(17) TF_R(29) TF_R(16) TF_R(24)
    x0 += k1;  x1 += k2c + 4u;
    TF_R(13) TF_R(15) TF_R(26) TF_R(6)
    x0 += k2c; x1 += k0 + 5u;
#undef TF_R
    unsigned bits = x0 ^ x1;
    float u = __uint_as_float((bits >> 9) | 0x3f800000u) - 1.0f;
    return (u < 0.5f) ? v * 2.0f : 0.0f;
}

// ---------------- dtype detection for edge_index ----------------
__global__ void k_detect(const void* __restrict__ ei) {
    const long long* p = (const long long*)ei;
    long long v = p[threadIdx.x];
    unsigned bad = __ballot_sync(0xffffffffu, (unsigned long long)v >= (unsigned long long)NN);
    __shared__ int s_bad;
    if (threadIdx.x == 0) s_bad = 0;
    __syncthreads();
    if ((threadIdx.x & 31) == 0 && bad) atomicOr(&s_bad, 1);
    __syncthreads();
    if (threadIdx.x == 0) g_idx64 = s_bad ? 0 : 1;
}

__device__ __forceinline__ void load_edge(const void* ei, int E, int e,
                                          int& src, int& dst) {
    if (g_idx64) {
        const long long* p = (const long long*)ei;
        src = (int)p[e];
        dst = (int)p[E + e];
    } else {
        const int* p = (const int*)ei;
        src = p[e];
        dst = p[E + e];
    }
}

// ---------------- init: copy x, zero deg, stack weights ----------------
__global__ void k_init(const float* __restrict__ x,
                       const float* __restrict__ Wl1, const float* __restrict__ Wr1,
                       const float* __restrict__ Wl2, const float* __restrict__ Wr2) {
    const int T0 = NN * 64;
    const int T1 = T0 + NN;
    const int T2 = T1 + 128 * 128;
    const int T3 = T2 + 256 * 304;
    for (int i = blockIdx.x * blockDim.x + threadIdx.x; i < T3;
         i += gridDim.x * blockDim.x) {
        if (i < T0) {
            int row = i >> 6, col = i & 63;
            g_A1[row * 128 + 64 + col] = x[i];
        } else if (i < T1) {
            g_degi[i - T0] = 0;
        } else if (i < T2) {
            int j = i - T1;
            g_Ws1[j] = (j < 64 * 128) ? Wl1[j] : Wr1[j - 64 * 128];
        } else {
            int j = i - T2;
            int row = j / 304, col = j - row * 304;
            float v = 0.f;
            if (col < 300)
                v = (row < 128) ? Wl2[row * 300 + col] : Wr2[(row - 128) * 300 + col];
            g_Ws2[j] = v;
        }
    }
}

// ---------------- CSR build ----------------
__global__ void k_hist(const void* __restrict__ ei, int E) {
    int e = blockIdx.x * blockDim.x + threadIdx.x;
    if (e >= E) return;
    int src, dst;
    load_edge(ei, E, e, src, dst);
    if ((unsigned)dst >= NN) return;
    atomicAdd(&g_degi[dst], 1);
}

// phase A: per-chunk (512) sums
__global__ void __launch_bounds__(512) k_scanA() {
    int b = blockIdx.x, t = threadIdx.x;
    int i = b * 512 + t;
    int v = (i < NN) ? g_degi[i] : 0;
#pragma unroll
    for (int o = 16; o; o >>= 1) v += __shfl_xor_sync(0xffffffffu, v, o);
    __shared__ int ws[16];
    if ((t & 31) == 0) ws[t >> 5] = v;
    __syncthreads();
    if (t < 16) {
        int s = ws[t];
#pragma unroll
        for (int o = 8; o; o >>= 1) s += __shfl_xor_sync(0xffffu, s, o);
        if (t == 0) g_part[b] = s;
    }
}

// phase B: exclusive scan of chunk sums (one small block)
__global__ void __launch_bounds__(128) k_scanB() {
    int t = threadIdx.x;
    int v = (t < SCAN_NB) ? g_part[t] : 0;
    int lane = t & 31, w = t >> 5;
    int x = v;
#pragma unroll
    for (int o = 1; o < 32; o <<= 1) {
        int y = __shfl_up_sync(0xffffffffu, x, o);
        if (lane >= o) x += y;
    }
    __shared__ int wsum[4];
    if (lane == 31) wsum[w] = x;
    __syncthreads();
    int add = 0;
    for (int i = 0; i < w; i++) add += wsum[i];
    int incl = x + add;
    if (t < SCAN_NB) g_partoff[t] = incl - v;
    if (t == SCAN_NB - 1) g_rowptr[NN] = incl;
}

// phase C: in-chunk exclusive scan + chunk offset -> rowptr/cursor
__global__ void __launch_bounds__(512) k_scanC() {
    int b = blockIdx.x, t = threadIdx.x;
    int i = b * 512 + t;
    int v = (i < NN) ? g_degi[i] : 0;
    int lane = t & 31, w = t >> 5;
    int x = v;
#pragma unroll
    for (int o = 1; o < 32; o <<= 1) {
        int y = __shfl_up_sync(0xffffffffu, x, o);
        if (lane >= o) x += y;
    }
    __shared__ int wsum[16];
    __shared__ int woff[16];
    if (lane == 31) wsum[w] = x;
    __syncthreads();
    if (t < 16) {
        int s = wsum[t];
        int xx = s;
#pragma unroll
        for (int o = 1; o < 16; o <<= 1) {
            int y = __shfl_up_sync(0xffffu, xx, o);
            if (t >= o) xx += y;
        }
        woff[t] = xx - s;
    }
    __syncthreads();
    int excl = (x - v) + woff[w] + g_partoff[b];
    if (i < NN) {
        g_rowptr[i] = excl;
        g_cursor[i] = excl;
    }
}

__global__ void k_place(const void* __restrict__ ei, int E) {
    int e = blockIdx.x * blockDim.x + threadIdx.x;
    if (e >= E) return;
    int src, dst;
    load_edge(ei, E, e, src, dst);
    if ((unsigned)src >= NN || (unsigned)dst >= NN) return;
    int pos = atomicAdd(&g_cursor[dst], 1);
    if (pos < EMAX) g_colsrc[pos] = src;
}

// ---------------- gather-aggregate, layer 1: mean of x over in-neighbors ----------------
__global__ void __launch_bounds__(256) k_gather1() {
    int warp = blockIdx.x * 8 + (threadIdx.x >> 5);
    int lane = threadIdx.x & 31;
    if (warp >= NN) return;
    int n0 = g_rowptr[warp], n1 = g_rowptr[warp + 1];
    float2 acc = make_float2(0.f, 0.f);
    for (int jb = n0; jb < n1; jb += 32) {
        int sid = (jb + lane < n1) ? g_colsrc[jb + lane] : 0;
        int m = min(32, n1 - jb);
        for (int k = 0; k < m; k++) {
            int s = __shfl_sync(0xffffffffu, sid, k);
            float2 v = *(const float2*)(g_A1 + s * 128 + 64 + lane * 2);
            acc.x += v.x; acc.y += v.y;
        }
    }
    float inv = 1.0f / fmaxf((float)(n1 - n0), 1.0f);
    acc.x *= inv; acc.y *= inv;
    *(float2*)(g_A1 + warp * 128 + lane * 2) = acc;
}

// ---------------- gather-aggregate, layer 2: mean of h over in-neighbors ----------------
__global__ void __launch_bounds__(256) k_gather2() {
    int warp = blockIdx.x * 8 + (threadIdx.x >> 5);
    int lane = threadIdx.x & 31;
    if (warp >= NN) return;
    int n0 = g_rowptr[warp], n1 = g_rowptr[warp + 1];
    float4 acc = make_float4(0.f, 0.f, 0.f, 0.f);
    for (int jb = n0; jb < n1; jb += 32) {
        int sid = (jb + lane < n1) ? g_colsrc[jb + lane] : 0;
        int m = min(32, n1 - jb);
        for (int k = 0; k < m; k++) {
            int s = __shfl_sync(0xffffffffu, sid, k);
            float4 v = *(const float4*)(g_A2 + (long long)s * 256 + 128 + lane * 4);
            acc.x += v.x; acc.y += v.y; acc.z += v.z; acc.w += v.w;
        }
    }
    float inv = 1.0f / fmaxf((float)(n1 - n0), 1.0f);
    acc.x *= inv; acc.y *= inv; acc.z *= inv; acc.w *= inv;
    *(float4*)(g_A2 + (long long)warp * 256 + lane * 4) = acc;
}

// ---------------- GEMM layer 1: h = relu(A1 @ Ws1 + b1), dropout, -> A2[:,128:256] ----------------
__global__ void __launch_bounds__(256) k_gemm1(const float* __restrict__ b1) {
    __shared__ float sA[64 * 32];
    __shared__ float sW[32 * 128];
    int tid = threadIdx.x;
    int row0 = blockIdx.x * 64;
    int cg = tid & 31;
    int rg = tid >> 5;
    float acc[8][4];
#pragma unroll
    for (int r = 0; r < 8; r++)
#pragma unroll
        for (int j = 0; j < 4; j++) acc[r][j] = 0.f;

    for (int ks = 0; ks < 128; ks += 32) {
        __syncthreads();
#pragma unroll
        for (int i = tid; i < 512; i += 256) {
            int r = i >> 3, c4 = i & 7;
            int gr = row0 + r;
            float4 v = (gr < NN) ? *(const float4*)(g_A1 + gr * 128 + ks + c4 * 4)
                                 : make_float4(0.f, 0.f, 0.f, 0.f);
            *(float4*)(sA + r * 32 + c4 * 4) = v;
        }
#pragma unroll
        for (int i = tid; i < 1024; i += 256) {
            int r = i >> 5, c4 = i & 31;
            *(float4*)(sW + r * 128 + c4 * 4) =
                *(const float4*)(g_Ws1 + (ks + r) * 128 + c4 * 4);
        }
        __syncthreads();
#pragma unroll
        for (int k4 = 0; k4 < 32; k4 += 4) {
            float4 a[8];
#pragma unroll
            for (int r = 0; r < 8; r++)
                a[r] = *(const float4*)(sA + (rg * 8 + r) * 32 + k4);
#pragma unroll
            for (int kk = 0; kk < 4; kk++) {
                float4 w = *(const float4*)(sW + (k4 + kk) * 128 + cg * 4);
#pragma unroll
                for (int r = 0; r < 8; r++) {
                    float av = ((const float*)&a[r])[kk];
                    acc[r][0] += av * w.x;
                    acc[r][1] += av * w.y;
                    acc[r][2] += av * w.z;
                    acc[r][3] += av * w.w;
                }
            }
        }
    }
    int c0 = cg * 4;
    float4 bv = *(const float4*)(b1 + c0);
#pragma unroll
    for (int r = 0; r < 8; r++) {
        int grow = row0 + rg * 8 + r;
        if (grow >= NN) continue;
        float4 h;
        h.x = fmaxf(acc[r][0] + bv.x, 0.f);
        h.y = fmaxf(acc[r][1] + bv.y, 0.f);
        h.z = fmaxf(acc[r][2] + bv.z, 0.f);
        h.w = fmaxf(acc[r][3] + bv.w, 0.f);
        unsigned base = (unsigned)grow * 128u + (unsigned)c0;
        h.x = tf_drop(h.x, base + 0u);
        h.y = tf_drop(h.y, base + 1u);
        h.z = tf_drop(h.z, base + 2u);
        h.w = tf_drop(h.w, base + 3u);
        *(float4*)(g_A2 + (long long)grow * 256 + 128 + c0) = h;
    }
}

// ---------------- GEMM layer 2: out = A2 @ Ws2 + b2 (logits) ----------------
__global__ void __launch_bounds__(256) k_gemm2(const float* __restrict__ b2,
                                               float* __restrict__ out) {
    __shared__ float sA[64 * 64];
    __shared__ float sW[64 * 64];
    int tid = threadIdx.x;
    int row0 = blockIdx.x * 64;
    int col0 = blockIdx.y * 64;
    int cg = tid & 31;
    int rg = tid >> 5;
    float acc[8][2];
#pragma unroll
    for (int r = 0; r < 8; r++) { acc[r][0] = 0.f; acc[r][1] = 0.f; }

    for (int ks = 0; ks < 256; ks += 64) {
        __syncthreads();
#pragma unroll
        for (int i = tid; i < 1024; i += 256) {
            int r = i >> 4, c4 = i & 15;
            int gr = row0 + r;
            float4 v = (gr < NN)
                ? *(const float4*)(g_A2 + (long long)gr * 256 + ks + c4 * 4)
                : make_float4(0.f, 0.f, 0.f, 0.f);
            *(float4*)(sA + r * 64 + c4 * 4) = v;
        }
#pragma unroll
        for (int i = tid; i < 1024; i += 256) {
            int r = i >> 4, c4 = i & 15;
            int gc = col0 + c4 * 4;
            float4 v = (gc < 304)
                ? *(const float4*)(g_Ws2 + (ks + r) * 304 + gc)
                : make_float4(0.f, 0.f, 0.f, 0.f);
            *(float4*)(sW + r * 64 + c4 * 4) = v;
        }
        __syncthreads();
#pragma unroll
        for (int k4 = 0; k4 < 64; k4 += 4) {
            float4 a[8];
#pragma unroll
            for (int r = 0; r < 8; r++)
                a[r] = *(const float4*)(sA + (rg * 8 + r) * 64 + k4);
#pragma unroll
            for (int kk = 0; kk < 4; kk++) {
                float2 w = *(const float2*)(sW + (k4 + kk) * 64 + cg * 2);
#pragma unroll
                for (int r = 0; r < 8; r++) {
                    float av = ((const float*)&a[r])[kk];
                    acc[r][0] += av * w.x;
                    acc[r][1] += av * w.y;
                }
            }
        }
    }
    int c0 = col0 + cg * 2;
    if (c0 < 300) {
        float2 bv = *(const float2*)(b2 + c0);
#pragma unroll
        for (int r = 0; r < 8; r++) {
            int grow = row0 + rg * 8 + r;
            if (grow >= NN) continue;
            float2 o;
            o.x = acc[r][0] + bv.x;
            o.y = acc[r][1] + bv.y;
            *(float2*)(out + (long long)grow * 300 + c0) = o;
        }
    }
}

// ---------------- log_softmax in-place, one warp per row of 300 ----------------
__global__ void __launch_bounds__(256) k_logsoftmax(float* __restrict__ out) {
    int gid = blockIdx.x * 256 + threadIdx.x;
    int row = gid >> 5;
    int lane = gid & 31;
    if (row >= NN) return;
    float* p = out + (long long)row * 300;
    float vals[10];
    float m = -3.4e38f;
#pragma unroll
    for (int i = 0; i < 10; i++) {
        int c = lane + i * 32;
        vals[i] = (c < 300) ? p[c] : -3.4e38f;
        m = fmaxf(m, vals[i]);
    }
#pragma unroll
    for (int o = 16; o; o >>= 1) m = fmaxf(m, __shfl_xor_sync(0xffffffffu, m, o));
    float s = 0.f;
#pragma unroll
    for (int i = 0; i < 10; i++) {
        int c = lane + i * 32;
        if (c < 300) s += __expf(vals[i] - m);
    }
#pragma unroll
    for (int o = 16; o; o >>= 1) s += __shfl_xor_sync(0xffffffffu, s, o);
    float lse = m + __logf(s);
#pragma unroll
    for (int i = 0; i < 10; i++) {
        int c = lane + i * 32;
        if (c < 300) p[c] = vals[i] - lse;
    }
}

// ---------------- launch ----------------
extern "C" void kernel_launch(void* const* d_in, const int* in_sizes, int n_in,
                              void* d_out, int out_size) {
    const float* x        = (const float*)d_in[0];
    const void*  ei       = (const void*)d_in[1];
    const float* Wl1      = (const float*)d_in[2];
    const float* Wr1      = (const float*)d_in[3];
    const float* b1       = (const float*)d_in[4];
    const float* Wl2      = (const float*)d_in[5];
    const float* Wr2      = (const float*)d_in[6];
    const float* b2       = (const float*)d_in[7];
    float* out            = (float*)d_out;
    int E = in_sizes[1] / 2;

    k_detect<<<1, 256>>>(ei);
    k_init<<<4096, 256>>>(x, Wl1, Wr1, Wl2, Wr2);
    k_hist<<<(E + 255) / 256, 256>>>(ei, E);
    k_scanA<<<SCAN_NB, 512>>>();
    k_scanB<<<1, 128>>>();
    k_scanC<<<SCAN_NB, 512>>>();
    k_place<<<(E + 255) / 256, 256>>>(ei, E);
    k_gather1<<<(NN + 7) / 8, 256>>>();
    k_gemm1<<<(NN + 63) / 64, 256>>>(b1);
    k_gather2<<<(NN + 7) / 8, 256>>>();
    dim3 g2((NN + 63) / 64, 5);
    k_gemm2<<<g2, 256>>>(b2, out);
    k_logsoftmax<<<(NN * 32 + 255) / 256, 256>>>(out);
}

// round 12
// speedup vs baseline: 1.3916x; 1.1317x over previous
#include <cuda_runtime.h>
#include <cuda_bf16.h>
#include <cstdint>

#define NN 50000
#define EMAX 1000000
#define SCAN_NB ((NN + 511) / 512)   // 98 chunks of 512

// ---------------- scratch (no allocations allowed) ----------------
static __device__ __align__(16) float g_A1[NN * 128];    // [agg(x) 0..63 | x 64..127]
static __device__ __align__(16) float g_A2[NN * 256];    // [agg(h) 0..127 | h 128..255]
static __device__ __align__(16) float g_Ws1t[128 * 128]; // transposed [n][k], k: [Wl1;Wr1]
static __device__ __align__(16) float g_Ws2t[384 * 256]; // transposed [n][k], padded n->384
static __device__ int g_idx64;
static __device__ int g_degi[NN];
static __device__ int g_rowptr[NN + 1];
static __device__ int g_cursor[NN];
static __device__ int g_colsrc[EMAX];
static __device__ int g_part[128];
static __device__ int g_partoff[128];

// ---------------- threefry2x32 dropout, JAX partitionable (o0 ^ o1) ----------------
__device__ __forceinline__ float tf_drop(float v, unsigned idx) {
    unsigned x0 = 0u, x1 = idx;
    const unsigned k0 = 0u, k1 = 42u;
    const unsigned k2c = 0u ^ 42u ^ 0x1BD11BDAu;
    x0 += k0; x1 += k1;
#define TF_R(r) { x0 += x1; x1 = __funnelshift_l(x1, x1, (r)); x1 ^= x0; }
    TF_R(13) TF_R(15) TF_R(26) TF_R(6)
    x0 += k1;  x1 += k2c + 1u;
    TF_R(17) TF_R(29) TF_R(16) TF_R(24)
    x0 += k2c; x1 += k0 + 2u;
    TF_R(13) TF_R(15) TF_R(26) TF_R(6)
    x0 += k0;  x1 += k1 + 3u;
    TF_R(17) TF_R(29) TF_R(16) TF_R(24)
    x0 += k1;  x1 += k2c + 4u;
    TF_R(13) TF_R(15) TF_R(26) TF_R(6)
    x0 += k2c; x1 += k0 + 5u;
#undef TF_R
    unsigned bits = x0 ^ x1;
    float u = __uint_as_float((bits >> 9) | 0x3f800000u) - 1.0f;
    return (u < 0.5f) ? v * 2.0f : 0.0f;
}

// ---------------- mma.sync m16n8k16 bf16 (sm_80+ PTX, works on compute_100) ----------------
__device__ __forceinline__ void mma16816(float* c, const unsigned* a, const unsigned* b) {
    asm volatile(
        "mma.sync.aligned.m16n8k16.row.col.f32.bf16.bf16.f32 "
        "{%0,%1,%2,%3}, {%4,%5,%6,%7}, {%8,%9}, {%0,%1,%2,%3};"
        : "+f"(c[0]), "+f"(c[1]), "+f"(c[2]), "+f"(c[3])
        : "r"(a[0]), "r"(a[1]), "r"(a[2]), "r"(a[3]), "r"(b[0]), "r"(b[1]));
}

#define SSTR 36   // smem row stride (bf16 elems), 32 data + 4 pad

// convert fp32 [128 x 32] tile -> hi/lo bf16 smem tiles (stride SSTR)
__device__ __forceinline__ void cvt_tile(const float* __restrict__ src, int stride,
                                         int r0, int rowlim, int kb,
                                         ushort* hi, ushort* lo, int tid) {
    for (int i = tid; i < 1024; i += 256) {
        int r = i >> 3, c4 = (i & 7) * 4;
        int gr = r0 + r;
        float4 v = make_float4(0.f, 0.f, 0.f, 0.f);
        if (gr < rowlim) v = *(const float4*)(src + (long long)gr * stride + kb + c4);
        __nv_bfloat16 h0 = __float2bfloat16(v.x), h1 = __float2bfloat16(v.y);
        __nv_bfloat16 h2 = __float2bfloat16(v.z), h3 = __float2bfloat16(v.w);
        __nv_bfloat16 l0 = __float2bfloat16(v.x - __bfloat162float(h0));
        __nv_bfloat16 l1 = __float2bfloat16(v.y - __bfloat162float(h1));
        __nv_bfloat16 l2 = __float2bfloat16(v.z - __bfloat162float(h2));
        __nv_bfloat16 l3 = __float2bfloat16(v.w - __bfloat162float(h3));
        int o = r * SSTR + c4;
        *(unsigned*)(hi + o)     = ((unsigned)__bfloat16_as_ushort(h1) << 16) | __bfloat16_as_ushort(h0);
        *(unsigned*)(hi + o + 2) = ((unsigned)__bfloat16_as_ushort(h3) << 16) | __bfloat16_as_ushort(h2);
        *(unsigned*)(lo + o)     = ((unsigned)__bfloat16_as_ushort(l1) << 16) | __bfloat16_as_ushort(l0);
        *(unsigned*)(lo + o + 2) = ((unsigned)__bfloat16_as_ushort(l3) << 16) | __bfloat16_as_ushort(l2);
    }
}

// ---------------- dtype detection ----------------
__global__ void k_detect(const void* __restrict__ ei) {
    const long long* p = (const long long*)ei;
    long long v = p[threadIdx.x];
    unsigned bad = __ballot_sync(0xffffffffu, (unsigned long long)v >= (unsigned long long)NN);
    __shared__ int s_bad;
    if (threadIdx.x == 0) s_bad = 0;
    __syncthreads();
    if ((threadIdx.x & 31) == 0 && bad) atomicOr(&s_bad, 1);
    __syncthreads();
    if (threadIdx.x == 0) g_idx64 = s_bad ? 0 : 1;
}

__device__ __forceinline__ void load_edge(const void* ei, int E, int e, int& src, int& dst) {
    if (g_idx64) {
        const long long* p = (const long long*)ei;
        src = (int)p[e];
        dst = (int)p[E + e];
    } else {
        const int* p = (const int*)ei;
        src = p[e];
        dst = p[E + e];
    }
}

// ---------------- init: copy x, zero deg, transposed stacked weights ----------------
__global__ void k_init(const float* __restrict__ x,
                       const float* __restrict__ Wl1, const float* __restrict__ Wr1,
                       const float* __restrict__ Wl2, const float* __restrict__ Wr2) {
    const int T0 = NN * 64;
    const int T1 = T0 + NN;
    const int T2 = T1 + 128 * 128;
    const int T3 = T2 + 384 * 256;
    for (int i = blockIdx.x * blockDim.x + threadIdx.x; i < T3;
         i += gridDim.x * blockDim.x) {
        if (i < T0) {
            int row = i >> 6, col = i & 63;
            g_A1[row * 128 + 64 + col] = x[i];
        } else if (i < T1) {
            g_degi[i - T0] = 0;
        } else if (i < T2) {
            int j = i - T1;
            int n = j >> 7, k = j & 127;
            g_Ws1t[j] = (k < 64) ? Wl1[k * 128 + n] : Wr1[(k - 64) * 128 + n];
        } else {
            int j = i - T2;
            int n = j >> 8, k = j & 255;
            float v = 0.f;
            if (n < 300)
                v = (k < 128) ? Wl2[k * 300 + n] : Wr2[(k - 128) * 300 + n];
            g_Ws2t[j] = v;
        }
    }
}

// ---------------- CSR build ----------------
__global__ void k_hist(const void* __restrict__ ei, int E) {
    int e = blockIdx.x * blockDim.x + threadIdx.x;
    if (e >= E) return;
    int src, dst;
    load_edge(ei, E, e, src, dst);
    if ((unsigned)dst >= NN) return;
    atomicAdd(&g_degi[dst], 1);
}

__global__ void __launch_bounds__(512) k_scanA() {
    int b = blockIdx.x, t = threadIdx.x;
    int i = b * 512 + t;
    int v = (i < NN) ? g_degi[i] : 0;
#pragma unroll
    for (int o = 16; o; o >>= 1) v += __shfl_xor_sync(0xffffffffu, v, o);
    __shared__ int ws[16];
    if ((t & 31) == 0) ws[t >> 5] = v;
    __syncthreads();
    if (t < 16) {
        int s = ws[t];
#pragma unroll
        for (int o = 8; o; o >>= 1) s += __shfl_xor_sync(0xffffu, s, o);
        if (t == 0) g_part[b] = s;
    }
}

__global__ void __launch_bounds__(128) k_scanB() {
    int t = threadIdx.x;
    int v = (t < SCAN_NB) ? g_part[t] : 0;
    int lane = t & 31, w = t >> 5;
    int x = v;
#pragma unroll
    for (int o = 1; o < 32; o <<= 1) {
        int y = __shfl_up_sync(0xffffffffu, x, o);
        if (lane >= o) x += y;
    }
    __shared__ int wsum[4];
    if (lane == 31) wsum[w] = x;
    __syncthreads();
    int add = 0;
    for (int i = 0; i < w; i++) add += wsum[i];
    int incl = x + add;
    if (t < SCAN_NB) g_partoff[t] = incl - v;
    if (t == SCAN_NB - 1) g_rowptr[NN] = incl;
}

__global__ void __launch_bounds__(512) k_scanC() {
    int b = blockIdx.x, t = threadIdx.x;
    int i = b * 512 + t;
    int v = (i < NN) ? g_degi[i] : 0;
    int lane = t & 31, w = t >> 5;
    int x = v;
#pragma unroll
    for (int o = 1; o < 32; o <<= 1) {
        int y = __shfl_up_sync(0xffffffffu, x, o);
        if (lane >= o) x += y;
    }
    __shared__ int wsum[16];
    __shared__ int woff[16];
    if (lane == 31) wsum[w] = x;
    __syncthreads();
    if (t < 16) {
        int s = wsum[t];
        int xx = s;
#pragma unroll
        for (int o = 1; o < 16; o <<= 1) {
            int y = __shfl_up_sync(0xffffu, xx, o);
            if (t >= o) xx += y;
        }
        woff[t] = xx - s;
    }
    __syncthreads();
    int excl = (x - v) + woff[w] + g_partoff[b];
    if (i < NN) {
        g_rowptr[i] = excl;
        g_cursor[i] = excl;
    }
}

__global__ void k_place(const void* __restrict__ ei, int E) {
    int e = blockIdx.x * blockDim.x + threadIdx.x;
    if (e >= E) return;
    int src, dst;
    load_edge(ei, E, e, src, dst);
    if ((unsigned)src >= NN || (unsigned)dst >= NN) return;
    int pos = atomicAdd(&g_cursor[dst], 1);
    if (pos < EMAX) g_colsrc[pos] = src;
}

// ---------------- gather-aggregate ----------------
__global__ void __launch_bounds__(256) k_gather1() {
    int warp = blockIdx.x * 8 + (threadIdx.x >> 5);
    int lane = threadIdx.x & 31;
    if (warp >= NN) return;
    int n0 = g_rowptr[warp], n1 = g_rowptr[warp + 1];
    float2 acc = make_float2(0.f, 0.f);
    for (int jb = n0; jb < n1; jb += 32) {
        int sid = (jb + lane < n1) ? g_colsrc[jb + lane] : 0;
        int m = min(32, n1 - jb);
        for (int k = 0; k < m; k++) {
            int s = __shfl_sync(0xffffffffu, sid, k);
            float2 v = *(const float2*)(g_A1 + s * 128 + 64 + lane * 2);
            acc.x += v.x; acc.y += v.y;
        }
    }
    float inv = 1.0f / fmaxf((float)(n1 - n0), 1.0f);
    acc.x *= inv; acc.y *= inv;
    *(float2*)(g_A1 + warp * 128 + lane * 2) = acc;
}

__global__ void __launch_bounds__(256) k_gather2() {
    int warp = blockIdx.x * 8 + (threadIdx.x >> 5);
    int lane = threadIdx.x & 31;
    if (warp >= NN) return;
    int n0 = g_rowptr[warp], n1 = g_rowptr[warp + 1];
    float4 acc = make_float4(0.f, 0.f, 0.f, 0.f);
    for (int jb = n0; jb < n1; jb += 32) {
        int sid = (jb + lane < n1) ? g_colsrc[jb + lane] : 0;
        int m = min(32, n1 - jb);
        for (int k = 0; k < m; k++) {
            int s = __shfl_sync(0xffffffffu, sid, k);
            float4 v = *(const float4*)(g_A2 + (long long)s * 256 + 128 + lane * 4);
            acc.x += v.x; acc.y += v.y; acc.z += v.z; acc.w += v.w;
        }
    }
    float inv = 1.0f / fmaxf((float)(n1 - n0), 1.0f);
    acc.x *= inv; acc.y *= inv; acc.z *= inv; acc.w *= inv;
    *(float4*)(g_A2 + (long long)warp * 256 + lane * 4) = acc;
}

// ---------------- bf16-split tensor-core GEMM mainloop (block 128x128, 8 warps) ----------------
// acc[2][8][4]: warp tile 32x64 = 2 m16-frags x 8 n8-frags.
__device__ __forceinline__ void mma_block(const float* Ap, int astr, int row0,
                                          const float* Bp, int bstr, int ncol0,
                                          int nchunks, float acc[2][8][4],
                                          ushort* sAhi, ushort* sAlo,
                                          ushort* sBhi, ushort* sBlo) {
    int tid = threadIdx.x;
    int lane = tid & 31, wid = tid >> 5;
    int warp_m = wid & 3, warp_n = wid >> 2;
    int g = lane >> 2, t2 = (lane & 3) * 2;

    for (int c = 0; c < nchunks; c++) {
        __syncthreads();
        int kb = c * 32;
        cvt_tile(Ap, astr, row0, NN, kb, sAhi, sAlo, tid);
        cvt_tile(Bp, bstr, ncol0, 1 << 30, kb, sBhi, sBlo, tid);
        __syncthreads();
#pragma unroll
        for (int kk = 0; kk < 32; kk += 16) {
            unsigned ah[2][4], al[2][4];
#pragma unroll
            for (int mf = 0; mf < 2; mf++) {
                int m = warp_m * 32 + mf * 16 + g;
                int k0 = kk + t2;
                ah[mf][0] = *(const unsigned*)(sAhi + m * SSTR + k0);
                ah[mf][1] = *(const unsigned*)(sAhi + (m + 8) * SSTR + k0);
                ah[mf][2] = *(const unsigned*)(sAhi + m * SSTR + k0 + 8);
                ah[mf][3] = *(const unsigned*)(sAhi + (m + 8) * SSTR + k0 + 8);
                al[mf][0] = *(const unsigned*)(sAlo + m * SSTR + k0);
                al[mf][1] = *(const unsigned*)(sAlo + (m + 8) * SSTR + k0);
                al[mf][2] = *(const unsigned*)(sAlo + m * SSTR + k0 + 8);
                al[mf][3] = *(const unsigned*)(sAlo + (m + 8) * SSTR + k0 + 8);
            }
#pragma unroll
            for (int nf = 0; nf < 8; nf++) {
                int n = warp_n * 64 + nf * 8 + g;
                int k0 = kk + t2;
                unsigned bh[2], bl[2];
                bh[0] = *(const unsigned*)(sBhi + n * SSTR + k0);
                bh[1] = *(const unsigned*)(sBhi + n * SSTR + k0 + 8);
                bl[0] = *(const unsigned*)(sBlo + n * SSTR + k0);
                bl[1] = *(const unsigned*)(sBlo + n * SSTR + k0 + 8);
#pragma unroll
                for (int mf = 0; mf < 2; mf++) {
                    mma16816(acc[mf][nf], ah[mf], bh);
                    mma16816(acc[mf][nf], ah[mf], bl);
                    mma16816(acc[mf][nf], al[mf], bh);
                }
            }
        }
    }
}

// ---------------- GEMM layer 1: h = drop(relu(A1 @ Ws1t^T + b1)) -> A2[:,128:256] ----------------
__global__ void __launch_bounds__(256) k_mgemm1(const float* __restrict__ b1) {
    __shared__ ushort sAhi[128 * SSTR], sAlo[128 * SSTR];
    __shared__ ushort sBhi[128 * SSTR], sBlo[128 * SSTR];
    float acc[2][8][4];
#pragma unroll
    for (int a = 0; a < 2; a++)
#pragma unroll
        for (int b = 0; b < 8; b++)
#pragma unroll
            for (int j = 0; j < 4; j++) acc[a][b][j] = 0.f;

    int row0 = blockIdx.x * 128;
    mma_block(g_A1, 128, row0, g_Ws1t, 128, 0, 4, acc, sAhi, sAlo, sBhi, sBlo);

    int tid = threadIdx.x;
    int lane = tid & 31, wid = tid >> 5;
    int warp_m = wid & 3, warp_n = wid >> 2;
    int g = lane >> 2, t2 = (lane & 3) * 2;
#pragma unroll
    for (int mf = 0; mf < 2; mf++) {
#pragma unroll
        for (int nf = 0; nf < 8; nf++) {
            int col = warp_n * 64 + nf * 8 + t2;
            float2 bv = *(const float2*)(b1 + col);
#pragma unroll
            for (int half = 0; half < 2; half++) {
                int row = row0 + warp_m * 32 + mf * 16 + g + half * 8;
                if (row < NN) {
                    float v0 = acc[mf][nf][half * 2 + 0] + bv.x;
                    float v1 = acc[mf][nf][half * 2 + 1] + bv.y;
                    unsigned base = (unsigned)row * 128u + (unsigned)col;
                    float2 h;
                    h.x = tf_drop(fmaxf(v0, 0.f), base + 0u);
                    h.y = tf_drop(fmaxf(v1, 0.f), base + 1u);
                    *(float2*)(g_A2 + (long long)row * 256 + 128 + col) = h;
                }
            }
        }
    }
}

// ---------------- GEMM layer 2: out = A2 @ Ws2t^T + b2 ----------------
__global__ void __launch_bounds__(256) k_mgemm2(const float* __restrict__ b2,
                                                float* __restrict__ out) {
    __shared__ ushort sAhi[128 * SSTR], sAlo[128 * SSTR];
    __shared__ ushort sBhi[128 * SSTR], sBlo[128 * SSTR];
    float acc[2][8][4];
#pragma unroll
    for (int a = 0; a < 2; a++)
#pragma unroll
        for (int b = 0; b < 8; b++)
#pragma unroll
            for (int j = 0; j < 4; j++) acc[a][b][j] = 0.f;

    int row0 = blockIdx.x * 128;
    int col0 = blockIdx.y * 128;
    mma_block(g_A2, 256, row0, g_Ws2t, 256, col0, 8, acc, sAhi, sAlo, sBhi, sBlo);

    int tid = threadIdx.x;
    int lane = tid & 31, wid = tid >> 5;
    int warp_m = wid & 3, warp_n = wid >> 2;
    int g = lane >> 2, t2 = (lane & 3) * 2;
#pragma unroll
    for (int mf = 0; mf < 2; mf++) {
#pragma unroll
        for (int nf = 0; nf < 8; nf++) {
            int col = col0 + warp_n * 64 + nf * 8 + t2;
            if (col < 300) {
                float2 bv = *(const float2*)(b2 + col);
#pragma unroll
                for (int half = 0; half < 2; half++) {
                    int row = row0 + warp_m * 32 + mf * 16 + g + half * 8;
                    if (row < NN) {
                        float2 o;
                        o.x = acc[mf][nf][half * 2 + 0] + bv.x;
                        o.y = acc[mf][nf][half * 2 + 1] + bv.y;
                        *(float2*)(out + (long long)row * 300 + col) = o;
                    }
                }
            }
        }
    }
}

// ---------------- log_softmax in-place, one warp per row of 300 ----------------
__global__ void __launch_bounds__(256) k_logsoftmax(float* __restrict__ out) {
    int gid = blockIdx.x * 256 + threadIdx.x;
    int row = gid >> 5;
    int lane = gid & 31;
    if (row >= NN) return;
    float* p = out + (long long)row * 300;
    float vals[10];
    float m = -3.4e38f;
#pragma unroll
    for (int i = 0; i < 10; i++) {
        int c = lane + i * 32;
        vals[i] = (c < 300) ? p[c] : -3.4e38f;
        m = fmaxf(m, vals[i]);
    }
#pragma unroll
    for (int o = 16; o; o >>= 1) m = fmaxf(m, __shfl_xor_sync(0xffffffffu, m, o));
    float s = 0.f;
#pragma unroll
    for (int i = 0; i < 10; i++) {
        int c = lane + i * 32;
        if (c < 300) s += __expf(vals[i] - m);
    }
#pragma unroll
    for (int o = 16; o; o >>= 1) s += __shfl_xor_sync(0xffffffffu, s, o);
    float lse = m + __logf(s);
#pragma unroll
    for (int i = 0; i < 10; i++) {
        int c = lane + i * 32;
        if (c < 300) p[c] = vals[i] - lse;
    }
}

// ---------------- launch ----------------
extern "C" void kernel_launch(void* const* d_in, const int* in_sizes, int n_in,
                              void* d_out, int out_size) {
    const float* x        = (const float*)d_in[0];
    const void*  ei       = (const void*)d_in[1];
    const float* Wl1      = (const float*)d_in[2];
    const float* Wr1      = (const float*)d_in[3];
    const float* b1       = (const float*)d_in[4];
    const float* Wl2      = (const float*)d_in[5];
    const float* Wr2      = (const float*)d_in[6];
    const float* b2       = (const float*)d_in[7];
    float* out            = (float*)d_out;
    int E = in_sizes[1] / 2;

    k_detect<<<1, 256>>>(ei);
    k_init<<<4096, 256>>>(x, Wl1, Wr1, Wl2, Wr2);
    k_hist<<<(E + 255) / 256, 256>>>(ei, E);
    k_scanA<<<SCAN_NB, 512>>>();
    k_scanB<<<1, 128>>>();
    k_scanC<<<SCAN_NB, 512>>>();
    k_place<<<(E + 255) / 256, 256>>>(ei, E);
    k_gather1<<<(NN + 7) / 8, 256>>>();
    k_mgemm1<<<(NN + 127) / 128, 256>>>(b1);
    k_gather2<<<(NN + 7) / 8, 256>>>();
    dim3 g2((NN + 127) / 128, 3);
    k_mgemm2<<<g2, 256>>>(b2, out);
    k_logsoftmax<<<(NN * 32 + 255) / 256, 256>>>(out);
}

// round 13
// speedup vs baseline: 1.4777x; 1.0619x over previous
#include <cuda_runtime.h>
#include <cuda_bf16.h>
#include <cstdint>

#define NN 50000
#define EMAX 1000000
#define SCAN_NB ((NN + 511) / 512)   // 98 chunks of 512

// ---------------- scratch: hi/lo bf16 number system (no allocations) ----------------
static __device__ __align__(16) ushort g_A1h[NN * 128];  // [agg(x) | x] hi
static __device__ __align__(16) ushort g_A1l[NN * 128];  // lo
static __device__ __align__(16) ushort g_A2h[NN * 256];  // [agg(h) | h] hi
static __device__ __align__(16) ushort g_A2l[NN * 256];  // lo
static __device__ __align__(16) ushort g_W1h[128 * 128]; // [Wl1;Wr1]^T hi
static __device__ __align__(16) ushort g_W1l[128 * 128];
static __device__ __align__(16) ushort g_W2h[384 * 256]; // [Wl2;Wr2]^T hi, n-padded
static __device__ __align__(16) ushort g_W2l[384 * 256];
static __device__ int g_idx64;
static __device__ int g_degi[NN];
static __device__ int g_rowptr[NN + 1];
static __device__ int g_cursor[NN];
static __device__ int g_colsrc[EMAX];
static __device__ int g_part[128];
static __device__ int g_partoff[128];

__device__ __forceinline__ void bsplit(float v, ushort& h, ushort& l) {
    __nv_bfloat16 hb = __float2bfloat16(v);
    h = __bfloat16_as_ushort(hb);
    l = __bfloat16_as_ushort(__float2bfloat16(v - __bfloat162float(hb)));
}
__device__ __forceinline__ float bjoin(ushort h, ushort l) {
    return __bfloat162float(__ushort_as_bfloat16(h)) +
           __bfloat162float(__ushort_as_bfloat16(l));
}

// ---------------- threefry2x32 dropout, JAX partitionable (o0 ^ o1) ----------------
__device__ __forceinline__ float tf_drop(float v, unsigned idx) {
    unsigned x0 = 0u, x1 = idx;
    const unsigned k0 = 0u, k1 = 42u;
    const unsigned k2c = 0u ^ 42u ^ 0x1BD11BDAu;
    x0 += k0; x1 += k1;
#define TF_R(r) { x0 += x1; x1 = __funnelshift_l(x1, x1, (r)); x1 ^= x0; }
    TF_R(13) TF_R(15) TF_R(26) TF_R(6)
    x0 += k1;  x1 += k2c + 1u;
    TF_R(17) TF_R(29) TF_R(16) TF_R(24)
    x0 += k2c; x1 += k0 + 2u;
    TF_R(13) TF_R(15) TF_R(26) TF_R(6)
    x0 += k0;  x1 += k1 + 3u;
    TF_R(17) TF_R(29) TF_R(16) TF_R(24)
    x0 += k1;  x1 += k2c + 4u;
    TF_R(13) TF_R(15) TF_R(26) TF_R(6)
    x0 += k2c; x1 += k0 + 5u;
#undef TF_R
    unsigned bits = x0 ^ x1;
    float u = __uint_as_float((bits >> 9) | 0x3f800000u) - 1.0f;
    return (u < 0.5f) ? v * 2.0f : 0.0f;
}

// ---------------- mma.sync m16n8k16 bf16 ----------------
__device__ __forceinline__ void mma16816(float* c, const unsigned* a, const unsigned* b) {
    asm volatile(
        "mma.sync.aligned.m16n8k16.row.col.f32.bf16.bf16.f32 "
        "{%0,%1,%2,%3}, {%4,%5,%6,%7}, {%8,%9}, {%0,%1,%2,%3};"
        : "+f"(c[0]), "+f"(c[1]), "+f"(c[2]), "+f"(c[3])
        : "r"(a[0]), "r"(a[1]), "r"(a[2]), "r"(a[3]), "r"(b[0]), "r"(b[1]));
}

#define SSTR 40   // smem row stride (ushorts): 32 data + 8 pad; 16B-aligned rows

// copy 128x32 ushort tile from global (row-major, given stride) into smem
__device__ __forceinline__ void copy_tile(const ushort* __restrict__ src, int stride,
                                          int r0, int rowlim, int kb,
                                          ushort* dst, int tid) {
    for (int i = tid; i < 512; i += 256) {
        int r = i >> 2, c8 = (i & 3) * 8;
        int gr = r0 + r;
        uint4 v = make_uint4(0u, 0u, 0u, 0u);
        if (gr < rowlim)
            v = *(const uint4*)(src + (long long)gr * stride + kb + c8);
        *(uint4*)(dst + r * SSTR + c8) = v;
    }
}

// ---------------- dtype detection ----------------
__global__ void k_detect(const void* __restrict__ ei) {
    const long long* p = (const long long*)ei;
    long long v = p[threadIdx.x];
    unsigned bad = __ballot_sync(0xffffffffu, (unsigned long long)v >= (unsigned long long)NN);
    __shared__ int s_bad;
    if (threadIdx.x == 0) s_bad = 0;
    __syncthreads();
    if ((threadIdx.x & 31) == 0 && bad) atomicOr(&s_bad, 1);
    __syncthreads();
    if (threadIdx.x == 0) g_idx64 = s_bad ? 0 : 1;
}

__device__ __forceinline__ void load_edge(const void* ei, int E, int e, int& src, int& dst) {
    if (g_idx64) {
        const long long* p = (const long long*)ei;
        src = (int)p[e];
        dst = (int)p[E + e];
    } else {
        const int* p = (const int*)ei;
        src = p[e];
        dst = p[E + e];
    }
}

// ---------------- init: split x + weights into hi/lo, zero deg ----------------
__global__ void k_init(const float* __restrict__ x,
                       const float* __restrict__ Wl1, const float* __restrict__ Wr1,
                       const float* __restrict__ Wl2, const float* __restrict__ Wr2) {
    const int T0 = NN * 64;
    const int T1 = T0 + NN;
    const int T2 = T1 + 128 * 128;
    const int T3 = T2 + 384 * 256;
    for (int i = blockIdx.x * blockDim.x + threadIdx.x; i < T3;
         i += gridDim.x * blockDim.x) {
        if (i < T0) {
            int row = i >> 6, col = i & 63;
            ushort h, l;
            bsplit(x[i], h, l);
            g_A1h[row * 128 + 64 + col] = h;
            g_A1l[row * 128 + 64 + col] = l;
        } else if (i < T1) {
            g_degi[i - T0] = 0;
        } else if (i < T2) {
            int j = i - T1;
            int n = j >> 7, k = j & 127;
            float v = (k < 64) ? Wl1[k * 128 + n] : Wr1[(k - 64) * 128 + n];
            ushort h, l;
            bsplit(v, h, l);
            g_W1h[j] = h;
            g_W1l[j] = l;
        } else {
            int j = i - T2;
            int n = j >> 8, k = j & 255;
            float v = 0.f;
            if (n < 300)
                v = (k < 128) ? Wl2[k * 300 + n] : Wr2[(k - 128) * 300 + n];
            ushort h, l;
            bsplit(v, h, l);
            g_W2h[j] = h;
            g_W2l[j] = l;
        }
    }
}

// ---------------- CSR build ----------------
__global__ void k_hist(const void* __restrict__ ei, int E) {
    int e = blockIdx.x * blockDim.x + threadIdx.x;
    if (e >= E) return;
    int src, dst;
    load_edge(ei, E, e, src, dst);
    if ((unsigned)dst >= NN) return;
    atomicAdd(&g_degi[dst], 1);
}

__global__ void __launch_bounds__(512) k_scanA() {
    int b = blockIdx.x, t = threadIdx.x;
    int i = b * 512 + t;
    int v = (i < NN) ? g_degi[i] : 0;
#pragma unroll
    for (int o = 16; o; o >>= 1) v += __shfl_xor_sync(0xffffffffu, v, o);
    __shared__ int ws[16];
    if ((t & 31) == 0) ws[t >> 5] = v;
    __syncthreads();
    if (t < 16) {
        int s = ws[t];
#pragma unroll
        for (int o = 8; o; o >>= 1) s += __shfl_xor_sync(0xffffu, s, o);
        if (t == 0) g_part[b] = s;
    }
}

__global__ void __launch_bounds__(128) k_scanB() {
    int t = threadIdx.x;
    int v = (t < SCAN_NB) ? g_part[t] : 0;
    int lane = t & 31, w = t >> 5;
    int x = v;
#pragma unroll
    for (int o = 1; o < 32; o <<= 1) {
        int y = __shfl_up_sync(0xffffffffu, x, o);
        if (lane >= o) x += y;
    }
    __shared__ int wsum[4];
    if (lane == 31) wsum[w] = x;
    __syncthreads();
    int add = 0;
    for (int i = 0; i < w; i++) add += wsum[i];
    int incl = x + add;
    if (t < SCAN_NB) g_partoff[t] = incl - v;
    if (t == SCAN_NB - 1) g_rowptr[NN] = incl;
}

__global__ void __launch_bounds__(512) k_scanC() {
    int b = blockIdx.x, t = threadIdx.x;
    int i = b * 512 + t;
    int v = (i < NN) ? g_degi[i] : 0;
    int lane = t & 31, w = t >> 5;
    int x = v;
#pragma unroll
    for (int o = 1; o < 32; o <<= 1) {
        int y = __shfl_up_sync(0xffffffffu, x, o);
        if (lane >= o) x += y;
    }
    __shared__ int wsum[16];
    __shared__ int woff[16];
    if (lane == 31) wsum[w] = x;
    __syncthreads();
    if (t < 16) {
        int s = wsum[t];
        int xx = s;
#pragma unroll
        for (int o = 1; o < 16; o <<= 1) {
            int y = __shfl_up_sync(0xffffu, xx, o);
            if (t >= o) xx += y;
        }
        woff[t] = xx - s;
    }
    __syncthreads();
    int excl = (x - v) + woff[w] + g_partoff[b];
    if (i < NN) {
        g_rowptr[i] = excl;
        g_cursor[i] = excl;
    }
}

__global__ void k_place(const void* __restrict__ ei, int E) {
    int e = blockIdx.x * blockDim.x + threadIdx.x;
    if (e >= E) return;
    int src, dst;
    load_edge(ei, E, e, src, dst);
    if ((unsigned)src >= NN || (unsigned)dst >= NN) return;
    int pos = atomicAdd(&g_cursor[dst], 1);
    if (pos < EMAX) g_colsrc[pos] = src;
}

// ---------------- gather-aggregate, layer 1: lane covers 2 cols of 64 ----------------
__global__ void __launch_bounds__(256) k_gather1() {
    int warp = blockIdx.x * 8 + (threadIdx.x >> 5);
    int lane = threadIdx.x & 31;
    if (warp >= NN) return;
    int n0 = g_rowptr[warp], n1 = g_rowptr[warp + 1];
    float a0 = 0.f, a1 = 0.f;
    for (int jb = n0; jb < n1; jb += 32) {
        int sid = (jb + lane < n1) ? g_colsrc[jb + lane] : 0;
        int m = min(32, n1 - jb);
        for (int k = 0; k < m; k++) {
            int s = __shfl_sync(0xffffffffu, sid, k);
            unsigned vh = *(const unsigned*)(g_A1h + s * 128 + 64 + lane * 2);
            unsigned vl = *(const unsigned*)(g_A1l + s * 128 + 64 + lane * 2);
            a0 += bjoin((ushort)(vh & 0xffff), (ushort)(vl & 0xffff));
            a1 += bjoin((ushort)(vh >> 16), (ushort)(vl >> 16));
        }
    }
    float inv = 1.0f / fmaxf((float)(n1 - n0), 1.0f);
    a0 *= inv; a1 *= inv;
    ushort h0, l0, h1, l1;
    bsplit(a0, h0, l0);
    bsplit(a1, h1, l1);
    *(unsigned*)(g_A1h + warp * 128 + lane * 2) = ((unsigned)h1 << 16) | h0;
    *(unsigned*)(g_A1l + warp * 128 + lane * 2) = ((unsigned)l1 << 16) | l0;
}

// ---------------- gather-aggregate, layer 2: lane covers 4 cols of 128 ----------------
__global__ void __launch_bounds__(256) k_gather2() {
    int warp = blockIdx.x * 8 + (threadIdx.x >> 5);
    int lane = threadIdx.x & 31;
    if (warp >= NN) return;
    int n0 = g_rowptr[warp], n1 = g_rowptr[warp + 1];
    float a0 = 0.f, a1 = 0.f, a2 = 0.f, a3 = 0.f;
    for (int jb = n0; jb < n1; jb += 32) {
        int sid = (jb + lane < n1) ? g_colsrc[jb + lane] : 0;
        int m = min(32, n1 - jb);
        for (int k = 0; k < m; k++) {
            int s = __shfl_sync(0xffffffffu, sid, k);
            uint2 vh = *(const uint2*)(g_A2h + (long long)s * 256 + 128 + lane * 4);
            uint2 vl = *(const uint2*)(g_A2l + (long long)s * 256 + 128 + lane * 4);
            a0 += bjoin((ushort)(vh.x & 0xffff), (ushort)(vl.x & 0xffff));
            a1 += bjoin((ushort)(vh.x >> 16), (ushort)(vl.x >> 16));
            a2 += bjoin((ushort)(vh.y & 0xffff), (ushort)(vl.y & 0xffff));
            a3 += bjoin((ushort)(vh.y >> 16), (ushort)(vl.y >> 16));
        }
    }
    float inv = 1.0f / fmaxf((float)(n1 - n0), 1.0f);
    a0 *= inv; a1 *= inv; a2 *= inv; a3 *= inv;
    ushort h0, l0, h1, l1, h2, l2, h3, l3;
    bsplit(a0, h0, l0);
    bsplit(a1, h1, l1);
    bsplit(a2, h2, l2);
    bsplit(a3, h3, l3);
    uint2 oh, ol;
    oh.x = ((unsigned)h1 << 16) | h0;  oh.y = ((unsigned)h3 << 16) | h2;
    ol.x = ((unsigned)l1 << 16) | l0;  ol.y = ((unsigned)l3 << 16) | l2;
    *(uint2*)(g_A2h + (long long)warp * 256 + lane * 4) = oh;
    *(uint2*)(g_A2l + (long long)warp * 256 + lane * 4) = ol;
}

// ---------------- bf16-split tensor-core GEMM mainloop (block 128x128, 8 warps) ----------------
__device__ __forceinline__ void mma_block(const ushort* Ah, const ushort* Al, int astr, int row0,
                                          const ushort* Bh, const ushort* Bl, int bstr, int ncol0,
                                          int nchunks, float acc[2][8][4],
                                          ushort* sAhi, ushort* sAlo,
                                          ushort* sBhi, ushort* sBlo) {
    int tid = threadIdx.x;
    int lane = tid & 31, wid = tid >> 5;
    int warp_m = wid & 3, warp_n = wid >> 2;
    int g = lane >> 2, t2 = (lane & 3) * 2;

    for (int c = 0; c < nchunks; c++) {
        __syncthreads();
        int kb = c * 32;
        copy_tile(Ah, astr, row0, NN, kb, sAhi, tid);
        copy_tile(Al, astr, row0, NN, kb, sAlo, tid);
        copy_tile(Bh, bstr, ncol0, 1 << 30, kb, sBhi, tid);
        copy_tile(Bl, bstr, ncol0, 1 << 30, kb, sBlo, tid);
        __syncthreads();
#pragma unroll
        for (int kk = 0; kk < 32; kk += 16) {
            unsigned ah[2][4], al[2][4];
#pragma unroll
            for (int mf = 0; mf < 2; mf++) {
                int m = warp_m * 32 + mf * 16 + g;
                int k0 = kk + t2;
                ah[mf][0] = *(const unsigned*)(sAhi + m * SSTR + k0);
                ah[mf][1] = *(const unsigned*)(sAhi + (m + 8) * SSTR + k0);
                ah[mf][2] = *(const unsigned*)(sAhi + m * SSTR + k0 + 8);
                ah[mf][3] = *(const unsigned*)(sAhi + (m + 8) * SSTR + k0 + 8);
                al[mf][0] = *(const unsigned*)(sAlo + m * SSTR + k0);
                al[mf][1] = *(const unsigned*)(sAlo + (m + 8) * SSTR + k0);
                al[mf][2] = *(const unsigned*)(sAlo + m * SSTR + k0 + 8);
                al[mf][3] = *(const unsigned*)(sAlo + (m + 8) * SSTR + k0 + 8);
            }
#pragma unroll
            for (int nf = 0; nf < 8; nf++) {
                int n = warp_n * 64 + nf * 8 + g;
                int k0 = kk + t2;
                unsigned bh[2], bl[2];
                bh[0] = *(const unsigned*)(sBhi + n * SSTR + k0);
                bh[1] = *(const unsigned*)(sBhi + n * SSTR + k0 + 8);
                bl[0] = *(const unsigned*)(sBlo + n * SSTR + k0);
                bl[1] = *(const unsigned*)(sBlo + n * SSTR + k0 + 8);
#pragma unroll
                for (int mf = 0; mf < 2; mf++) {
                    mma16816(acc[mf][nf], ah[mf], bh);
                    mma16816(acc[mf][nf], ah[mf], bl);
                    mma16816(acc[mf][nf], al[mf], bh);
                }
            }
        }
    }
}

// ---------------- GEMM layer 1: h = drop(relu(A1 @ W1^T + b1)) -> A2h/l[:,128:256] ----------------
__global__ void __launch_bounds__(256) k_mgemm1(const float* __restrict__ b1) {
    __shared__ ushort sAhi[128 * SSTR], sAlo[128 * SSTR];
    __shared__ ushort sBhi[128 * SSTR], sBlo[128 * SSTR];
    float acc[2][8][4];
#pragma unroll
    for (int a = 0; a < 2; a++)
#pragma unroll
        for (int b = 0; b < 8; b++)
#pragma unroll
            for (int j = 0; j < 4; j++) acc[a][b][j] = 0.f;

    int row0 = blockIdx.x * 128;
    mma_block(g_A1h, g_A1l, 128, row0, g_W1h, g_W1l, 128, 0, 4, acc, sAhi, sAlo, sBhi, sBlo);

    int tid = threadIdx.x;
    int lane = tid & 31, wid = tid >> 5;
    int warp_m = wid & 3, warp_n = wid >> 2;
    int g = lane >> 2, t2 = (lane & 3) * 2;
#pragma unroll
    for (int mf = 0; mf < 2; mf++) {
#pragma unroll
        for (int nf = 0; nf < 8; nf++) {
            int col = warp_n * 64 + nf * 8 + t2;
            float2 bv = *(const float2*)(b1 + col);
#pragma unroll
            for (int half = 0; half < 2; half++) {
                int row = row0 + warp_m * 32 + mf * 16 + g + half * 8;
                if (row < NN) {
                    float v0 = acc[mf][nf][half * 2 + 0] + bv.x;
                    float v1 = acc[mf][nf][half * 2 + 1] + bv.y;
                    unsigned base = (unsigned)row * 128u + (unsigned)col;
                    float h0 = tf_drop(fmaxf(v0, 0.f), base + 0u);
                    float h1 = tf_drop(fmaxf(v1, 0.f), base + 1u);
                    ushort hh0, ll0, hh1, ll1;
                    bsplit(h0, hh0, ll0);
                    bsplit(h1, hh1, ll1);
                    long long o = (long long)row * 256 + 128 + col;
                    *(unsigned*)(g_A2h + o) = ((unsigned)hh1 << 16) | hh0;
                    *(unsigned*)(g_A2l + o) = ((unsigned)ll1 << 16) | ll0;
                }
            }
        }
    }
}

// ---------------- GEMM layer 2: out = A2 @ W2^T + b2 ----------------
__global__ void __launch_bounds__(256) k_mgemm2(const float* __restrict__ b2,
                                                float* __restrict__ out) {
    __shared__ ushort sAhi[128 * SSTR], sAlo[128 * SSTR];
    __shared__ ushort sBhi[128 * SSTR], sBlo[128 * SSTR];
    float acc[2][8][4];
#pragma unroll
    for (int a = 0; a < 2; a++)
#pragma unroll
        for (int b = 0; b < 8; b++)
#pragma unroll
            for (int j = 0; j < 4; j++) acc[a][b][j] = 0.f;

    int row0 = blockIdx.x * 128;
    int col0 = blockIdx.y * 128;
    mma_block(g_A2h, g_A2l, 256, row0, g_W2h, g_W2l, 256, col0, 8, acc, sAhi, sAlo, sBhi, sBlo);

    int tid = threadIdx.x;
    int lane = tid & 31, wid = tid >> 5;
    int warp_m = wid & 3, warp_n = wid >> 2;
    int g = lane >> 2, t2 = (lane & 3) * 2;
#pragma unroll
    for (int mf = 0; mf < 2; mf++) {
#pragma unroll
        for (int nf = 0; nf < 8; nf++) {
            int col = col0 + warp_n * 64 + nf * 8 + t2;
            if (col < 300) {
                float2 bv = *(const float2*)(b2 + col);
#pragma unroll
                for (int half = 0; half < 2; half++) {
                    int row = row0 + warp_m * 32 + mf * 16 + g + half * 8;
                    if (row < NN) {
                        float2 o;
                        o.x = acc[mf][nf][half * 2 + 0] + bv.x;
                        o.y = acc[mf][nf][half * 2 + 1] + bv.y;
                        *(float2*)(out + (long long)row * 300 + col) = o;
                    }
                }
            }
        }
    }
}

// ---------------- log_softmax in-place, one warp per row of 300 ----------------
__global__ void __launch_bounds__(256) k_logsoftmax(float* __restrict__ out) {
    int gid = blockIdx.x * 256 + threadIdx.x;
    int row = gid >> 5;
    int lane = gid & 31;
    if (row >= NN) return;
    float* p = out + (long long)row * 300;
    float vals[10];
    float m = -3.4e38f;
#pragma unroll
    for (int i = 0; i < 10; i++) {
        int c = lane + i * 32;
        vals[i] = (c < 300) ? p[c] : -3.4e38f;
        m = fmaxf(m, vals[i]);
    }
#pragma unroll
    for (int o = 16; o; o >>= 1) m = fmaxf(m, __shfl_xor_sync(0xffffffffu, m, o));
    float s = 0.f;
#pragma unroll
    for (int i = 0; i < 10; i++) {
        int c = lane + i * 32;
        if (c < 300) s += __expf(vals[i] - m);
    }
#pragma unroll
    for (int o = 16; o; o >>= 1) s += __shfl_xor_sync(0xffffffffu, s, o);
    float lse = m + __logf(s);
#pragma unroll
    for (int i = 0; i < 10; i++) {
        int c = lane + i * 32;
        if (c < 300) p[c] = vals[i] - lse;
    }
}

// ---------------- launch ----------------
extern "C" void kernel_launch(void* const* d_in, const int* in_sizes, int n_in,
                              void* d_out, int out_size) {
    const float* x        = (const float*)d_in[0];
    const void*  ei       = (const void*)d_in[1];
    const float* Wl1      = (const float*)d_in[2];
    const float* Wr1      = (const float*)d_in[3];
    const float* b1       = (const float*)d_in[4];
    const float* Wl2      = (const float*)d_in[5];
    const float* Wr2      = (const float*)d_in[6];
    const float* b2       = (const float*)d_in[7];
    float* out            = (float*)d_out;
    int E = in_sizes[1] / 2;

    k_detect<<<1, 256>>>(ei);
    k_init<<<4096, 256>>>(x, Wl1, Wr1, Wl2, Wr2);
    k_hist<<<(E + 255) / 256, 256>>>(ei, E);
    k_scanA<<<SCAN_NB, 512>>>();
    k_scanB<<<1, 128>>>();
    k_scanC<<<SCAN_NB, 512>>>();
    k_place<<<(E + 255) / 256, 256>>>(ei, E);
    k_gather1<<<(NN + 7) / 8, 256>>>();
    k_mgemm1<<<(NN + 127) / 128, 256>>>(b1);
    k_gather2<<<(NN + 7) / 8, 256>>>();
    dim3 g2((NN + 127) / 128, 3);
    k_mgemm2<<<g2, 256>>>(b2, out);
    k_logsoftmax<<<(NN * 32 + 255) / 256, 256>>>(out);
}